// round 3
// baseline (speedup 1.0000x reference)
#include <cuda_runtime.h>
#include <cstdint>
#include <cstddef>

#define SEQ   2048
#define BATCH 64
#define DIN   512
#define HID   512
#define KTOT  1024          // DIN + HID
#define NBLK  128
#define NTHR  512
#define UNITS 4             // hidden units per block
#define NR    16            // UNITS * 4 gates
#define NKT   8             // k tiles per step
#define KT    128           // floats per k tile
#define KP2   64            // float2 per k tile
#define AST   66            // A row stride in float2 (padded, conflict-free)
#define WST   514           // W row stride in float2 (padded)

// smem bytes: W 16*514*8 + A 2*64*66*8 + b 64 + g 64*17*4 + c 256*4
#define SMEM_BYTES (16*514*8 + 2*64*66*8 + 64 + 64*17*4 + 256*4)

// ---- persistent global state (scratch via __device__ globals; no allocs) ----
__device__ float    g_h[2][BATCH * HID];   // ping-pong hidden state
__device__ unsigned g_arrive;
__device__ volatile unsigned g_epoch;
__device__ unsigned g_done;

// ---- helpers ----
__device__ __forceinline__ void fma2(unsigned long long& acc,
                                     unsigned long long a,
                                     unsigned long long b) {
    asm volatile("fma.rn.f32x2 %0, %1, %2, %0;" : "+l"(acc) : "l"(a), "l"(b));
}
__device__ __forceinline__ float2 unpk(unsigned long long v) {
    float2 f;
    asm("mov.b64 {%0, %1}, %2;" : "=f"(f.x), "=f"(f.y) : "l"(v));
    return f;
}
__device__ __forceinline__ float sigmoidf_(float x) {
    return 1.0f / (1.0f + __expf(-x));
}
__device__ __forceinline__ void cp_async16(uint32_t dst, const void* src) {
    asm volatile("cp.async.cg.shared.global [%0], [%1], 16;" :: "r"(dst), "l"(src));
}
__device__ __forceinline__ void cp_commit() {
    asm volatile("cp.async.commit_group;");
}

// Grid barrier: monotonic epoch within a launch; state reset at kernel exit so
// every graph replay sees identical initial state (determinism requirement).
__device__ __forceinline__ void grid_barrier(unsigned k) {
    __syncthreads();
    if (threadIdx.x == 0) {
        __threadfence();
        unsigned prev = atomicAdd(&g_arrive, 1u);
        if (prev == NBLK - 1) {
            g_arrive = 0u;          // only last arriver touches it; others spin on epoch
            __threadfence();
            g_epoch = k;
        } else {
            while (g_epoch < k) { }
            __threadfence();
        }
    }
    __syncthreads();
}

__global__ void __launch_bounds__(NTHR, 1)
lstm_kernel(const float* __restrict__ x,
            const float* __restrict__ Wf_, const float* __restrict__ bf_,
            const float* __restrict__ Wi_, const float* __restrict__ bi_,
            const float* __restrict__ Wg_, const float* __restrict__ bg_,
            const float* __restrict__ Wo_, const float* __restrict__ bo_,
            float* __restrict__ out)
{
    extern __shared__ float smem[];
    float2* Wsm = (float2*)smem;                   // [NR][WST]
    float2* Asm = Wsm + NR * WST;                  // [2][64][AST]
    float*  bsm = (float*)(Asm + 2 * 64 * AST);    // [16]
    float*  gsm = bsm + 16;                        // [64][17]
    float*  csm = gsm + 64 * 17;                   // [4][64]

    const int tid = threadIdx.x;
    const int j0  = blockIdx.x * UNITS;

    // ---- one-time: load this block's 16 gate rows (K=1024 each) into SMEM ----
    {
        const float* Wptr[4] = { Wf_, Wi_, Wg_, Wo_ };
        for (int idx = tid; idx < NR * (KTOT / 2); idx += NTHR) {
            int rr = idx >> 9;          // row 0..15  (r = u*4 + g)
            int kp = idx & 511;         // float2 index 0..511
            int u = rr >> 2, gg = rr & 3;
            const float2* W2 = (const float2*)(Wptr[gg] + (size_t)(j0 + u) * KTOT);
            Wsm[rr * WST + kp] = W2[kp];
        }
        if (tid < NR) {
            int u = tid >> 2, gg = tid & 3;
            const float* bp = (gg == 0) ? bf_ : (gg == 1) ? bi_ : (gg == 2) ? bg_ : bo_;
            bsm[tid] = bp[j0 + u];
        }
        if (tid < 256) {
            csm[tid] = 0.0f;                               // c0 = 0
            int b = tid & 63, u = tid >> 6;
            g_h[0][b * HID + j0 + u] = 0.0f;               // h0 = 0 (this block's slice)
        }
    }

    const int r   = tid & 15;       // gate row within block (u*4+g)
    const int bgp = tid >> 4;       // 0..31
    const int b0  = bgp;
    const int b1  = bgp + 32;

    const uint32_t asm_base = (uint32_t)__cvta_generic_to_shared(Asm);

    for (int t = 0; t < SEQ; ++t) {
        grid_barrier((unsigned)(t + 1));   // h_{t-1} (or init zeros) now globally visible

        const int p = t & 1;
        const float* __restrict__ hprev = g_h[p];
        const float* __restrict__ xrow  = x + (size_t)t * BATCH * DIN;

        auto stage = [&](int kt) {
            const int   buf = kt & 1;
            const float* src = (kt < 4) ? (xrow + kt * KT) : (hprev + (kt - 4) * KT);
            #pragma unroll
            for (int c = 0; c < 4; ++c) {
                int idx = tid + c * NTHR;      // 0..2047 (64 rows x 32 16B-chunks)
                int row = idx >> 5;
                int c16 = idx & 31;
                const float* g = src + row * 512 + c16 * 4;
                uint32_t d = asm_base + (uint32_t)(((buf * 64 + row) * AST) * 8 + c16 * 16);
                cp_async16(d, g);
            }
            cp_commit();
        };

        stage(0);

        unsigned long long acc0 = 0ull, acc1 = 0ull;

        for (int kt = 0; kt < NKT; ++kt) {
            if (kt + 1 < NKT) {
                stage(kt + 1);
                asm volatile("cp.async.wait_group 1;");
            } else {
                asm volatile("cp.async.wait_group 0;");
            }
            __syncthreads();

            const float2* wrow = Wsm + r * WST + kt * KP2;
            const float2* a0p  = Asm + ((kt & 1) * 64 + b0) * AST;
            const float2* a1p  = Asm + ((kt & 1) * 64 + b1) * AST;
            #pragma unroll
            for (int kp = 0; kp < KP2; kp += 2) {
                ulonglong2 w  = *(const ulonglong2*)(wrow + kp);
                ulonglong2 a0 = *(const ulonglong2*)(a0p + kp);
                ulonglong2 a1 = *(const ulonglong2*)(a1p + kp);
                fma2(acc0, a0.x, w.x);
                fma2(acc1, a1.x, w.x);
                fma2(acc0, a0.y, w.y);
                fma2(acc1, a1.y, w.y);
            }
            __syncthreads();
        }

        // gate pre-activations -> smem exchange
        {
            float2 s0 = unpk(acc0), s1 = unpk(acc1);
            float bias = bsm[r];
            gsm[b0 * 17 + r] = s0.x + s0.y + bias;
            gsm[b1 * 17 + r] = s1.x + s1.y + bias;
            acc0 = 0ull; acc1 = 0ull;
        }
        __syncthreads();

        // cell/hidden update: one thread per (batch, unit)
        if (tid < 256) {
            int b = tid & 63, u = tid >> 6;
            float pf = gsm[b * 17 + u * 4 + 0];
            float pi = gsm[b * 17 + u * 4 + 1];
            float pg = gsm[b * 17 + u * 4 + 2];
            float po = gsm[b * 17 + u * 4 + 3];
            float fg = sigmoidf_(pf);
            float ig = sigmoidf_(pi);
            float gg = tanhf(pg);
            float og = sigmoidf_(po);
            float c  = fg * csm[u * 64 + b] + ig * gg;
            csm[u * 64 + b] = c;
            float h  = og * tanhf(c);
            g_h[p ^ 1][b * HID + j0 + u] = h;
            out[((size_t)t * BATCH + b) * HID + j0 + u] = h;
            if (t == SEQ - 1) {
                size_t base = (size_t)SEQ * BATCH * HID;
                out[base + (size_t)b * HID + j0 + u] = h;                    // hx
                out[base + (size_t)BATCH * HID + (size_t)b * HID + j0 + u] = c; // cx
            }
        }
        // next grid_barrier begins with __syncthreads(), covering epilogue writes
    }

    // ---- reset barrier state so the next graph replay starts clean ----
    __syncthreads();
    if (tid == 0) {
        __threadfence();
        unsigned prev = atomicAdd(&g_done, 1u);
        if (prev == NBLK - 1) {
            g_done   = 0u;
            g_arrive = 0u;
            g_epoch  = 0u;
            __threadfence();
        }
    }
}

extern "C" void kernel_launch(void* const* d_in, const int* in_sizes, int n_in,
                              void* d_out, int out_size)
{
    const float* x  = (const float*)d_in[0];
    const float* Wf = (const float*)d_in[1];
    const float* bf = (const float*)d_in[2];
    const float* Wi = (const float*)d_in[3];
    const float* bi = (const float*)d_in[4];
    const float* Wg = (const float*)d_in[5];
    const float* bg = (const float*)d_in[6];
    const float* Wo = (const float*)d_in[7];
    const float* bo = (const float*)d_in[8];
    float* out = (float*)d_out;

    cudaFuncSetAttribute(lstm_kernel,
                         cudaFuncAttributeMaxDynamicSharedMemorySize, SMEM_BYTES);
    lstm_kernel<<<NBLK, NTHR, SMEM_BYTES>>>(x, Wf, bf, Wi, bi, Wg, bg, Wo, bo, out);
}

// round 5
// speedup vs baseline: 1.0010x; 1.0010x over previous
#include <cuda_runtime.h>
#include <cstdint>
#include <cstddef>

#define SEQ   2048
#define BATCH 64
#define DIN   512
#define HID   512
#define NBLK  128
#define NTHR  512
#define UNITS 4
#define NR    16

#define WST   1028        // W row stride in floats (16B-aligned, +4 bank skew)
#define KT    64          // A tile K-width (floats)
#define AST   68          // A tile row stride in floats (16B-aligned, +4 bank skew)
#define KG    256         // K per group
#define PST   20          // psm row stride (floats)

// shared layout (float offsets)
#define SM_W  0
#define SM_A  (16*WST)                  // 8 tile buffers [8][64][AST]
#define SM_P  (SM_A + 8*64*AST)         // psm [4][64][PST]
#define SM_B  (SM_P + 4*64*PST)         // bias [16]
#define SM_C  (SM_B + 16)               // cell [256]
#define SM_TOT (SM_C + 256)
#define SMEM_BYTES (SM_TOT*4)           // 226,624 B

// ---- persistent scratch (no allocs) ----
__device__ float             g_h[2][BATCH * HID];   // ping-pong hidden state
__device__ volatile unsigned g_flags[NBLK * 64];    // one flag per block, 256B stride
__device__ unsigned          g_done;

// ---- helpers ----
__device__ __forceinline__ void fma2(unsigned long long& acc,
                                     unsigned long long a,
                                     unsigned long long b) {
    asm volatile("fma.rn.f32x2 %0, %1, %2, %0;" : "+l"(acc) : "l"(a), "l"(b));
}
__device__ __forceinline__ float2 unpk(unsigned long long v) {
    float2 f;
    asm("mov.b64 {%0, %1}, %2;" : "=f"(f.x), "=f"(f.y) : "l"(v));
    return f;
}
__device__ __forceinline__ float sigmoidf_(float x) { return 1.0f / (1.0f + __expf(-x)); }
__device__ __forceinline__ void cp_async16(uint32_t dst, const void* src) {
    asm volatile("cp.async.cg.shared.global [%0], [%1], 16;" :: "r"(dst), "l"(src));
}
__device__ __forceinline__ void cp_commit() {
    asm volatile("cp.async.commit_group;" ::: "memory");
}
__device__ __forceinline__ void cp_wait1() {
    asm volatile("cp.async.wait_group 1;" ::: "memory");
}
__device__ __forceinline__ void cp_wait0() {
    asm volatile("cp.async.wait_group 0;" ::: "memory");
}
__device__ __forceinline__ void barx(int id, int cnt) {
    asm volatile("bar.sync %0, %1;" :: "r"(id), "r"(cnt) : "memory");
}

__global__ void __launch_bounds__(NTHR, 1)
lstm_kernel(const float* __restrict__ x,
            const float* __restrict__ Wf_, const float* __restrict__ bf_,
            const float* __restrict__ Wi_, const float* __restrict__ bi_,
            const float* __restrict__ Wg_, const float* __restrict__ bg_,
            const float* __restrict__ Wo_, const float* __restrict__ bo_,
            float* __restrict__ out)
{
    extern __shared__ float smem[];
    float* Wsm   = smem + SM_W;
    float* Atile = smem + SM_A;
    float* psm   = smem + SM_P;
    float* bsm   = smem + SM_B;
    float* csm   = smem + SM_C;

    const int tid = threadIdx.x;
    const int bid = blockIdx.x;
    const int j0  = bid * UNITS;

    // ---- init: weights/bias into smem, h0/c0 zero, publish readiness flag ----
    {
        const float* Wptr[4] = { Wf_, Wi_, Wg_, Wo_ };
        for (int idx = tid; idx < 16 * 256; idx += NTHR) {   // 16 rows x 256 float4
            int rr = idx >> 8;
            int c4 = idx & 255;
            int u = rr >> 2, gg = rr & 3;
            const float4* src = (const float4*)(Wptr[gg] + (size_t)(j0 + u) * 1024);
            *(float4*)(Wsm + rr * WST + c4 * 4) = src[c4];
        }
        if (tid < NR) {
            int u = tid >> 2, gg = tid & 3;
            const float* bp = (gg == 0) ? bf_ : (gg == 1) ? bi_ : (gg == 2) ? bg_ : bo_;
            bsm[tid] = bp[j0 + u];
        }
        if (tid < 256) {
            csm[tid] = 0.0f;
            int b = tid & 63, u = tid >> 6;
            g_h[0][b * HID + j0 + u] = 0.0f;
            __threadfence();                 // writer-side release (R3 discipline)
        }
    }
    __syncthreads();
    if (tid == 0) {
        __threadfence();                     // signaler-side release
        g_flags[bid * 64] = 1u;              // volatile store: "h0 slice visible"
    }

    // ---- GEMM thread decomposition ----
    const int g     = tid >> 7;          // K-group 0..3 (0,1 = x-part; 2,3 = h-part)
    const int gt    = tid & 127;         // thread within group
    const int wb    = gt >> 5;           // warp within group
    const int lane  = gt & 31;
    const int rg    = lane >> 2;         // row 0..7 (also rg+8)
    const int bg    = lane & 3;
    const int bbase = wb * 16 + bg;      // batches bbase + {0,4,8,12}

    const uint32_t a_base = (uint32_t)__cvta_generic_to_shared(Atile);

    for (int t = 0; t < SEQ; ++t) {
        const int p = t & 1;
        const float* __restrict__ hprev = g_h[p];
        const float* __restrict__ xrow  = x + (size_t)t * BATCH * DIN;

        // ---- h-half waits until every block published h_{t-1} ----
        if (g >= 2) {
            if (tid < 384) {               // group 2's 128 threads poll one flag each
                const unsigned target = (unsigned)(t + 1);
                while (g_flags[(tid - 256) * 64] < target) { }
            }
            __threadfence();               // consumer-side acquire (R3 discipline)
            barx(5, 256);                  // release both h-groups (warps 8..15)
        }

        auto stage = [&](int jt) {
            const int k0 = g * KG + jt * KT;
            const float* src = (k0 < DIN) ? (xrow + k0) : (hprev + (k0 - DIN));
            const int bufrow = (g * 2 + (jt & 1)) * 64;
            #pragma unroll
            for (int n = 0; n < 8; ++n) {
                int c   = gt + n * 128;          // 0..1023
                int b   = c >> 4;
                int off = (c & 15) * 4;          // float offset in tile row
                cp_async16(a_base + (uint32_t)((bufrow + b) * AST + off) * 4u,
                           src + b * 512 + off);
            }
            cp_commit();
        };

        unsigned long long a00 = 0, a01 = 0, a02 = 0, a03 = 0;
        unsigned long long a10 = 0, a11 = 0, a12 = 0, a13 = 0;

        stage(0); stage(1);

        const int barid = g + 1;
        for (int jt = 0; jt < 4; ++jt) {
            if (jt < 3) cp_wait1();
            else        cp_wait0();
            barx(barid, 128);                      // tile jt visible to whole group

            const float* wp0 = Wsm + rg * WST + g * KG + jt * KT;
            const float* wp1 = wp0 + 8 * WST;
            const float* ap  = Atile + (size_t)((g * 2 + (jt & 1)) * 64 + bbase) * AST;

            #pragma unroll
            for (int kq = 0; kq < 16; ++kq) {
                ulonglong2 w0 = *(const ulonglong2*)(wp0 + kq * 4);
                ulonglong2 w1 = *(const ulonglong2*)(wp1 + kq * 4);
                ulonglong2 b0 = *(const ulonglong2*)(ap + 0 * 4 * AST + kq * 4);
                ulonglong2 b1 = *(const ulonglong2*)(ap + 1 * 4 * AST + kq * 4);
                ulonglong2 b2 = *(const ulonglong2*)(ap + 2 * 4 * AST + kq * 4);
                ulonglong2 b3 = *(const ulonglong2*)(ap + 3 * 4 * AST + kq * 4);
                fma2(a00, b0.x, w0.x); fma2(a00, b0.y, w0.y);
                fma2(a01, b1.x, w0.x); fma2(a01, b1.y, w0.y);
                fma2(a02, b2.x, w0.x); fma2(a02, b2.y, w0.y);
                fma2(a03, b3.x, w0.x); fma2(a03, b3.y, w0.y);
                fma2(a10, b0.x, w1.x); fma2(a10, b0.y, w1.y);
                fma2(a11, b1.x, w1.x); fma2(a11, b1.y, w1.y);
                fma2(a12, b2.x, w1.x); fma2(a12, b2.y, w1.y);
                fma2(a13, b3.x, w1.x); fma2(a13, b3.y, w1.y);
            }

            if (jt < 2) {
                barx(barid, 128);                  // group done reading buf (jt)
                stage(jt + 2);                     // overwrite it with tile jt+2
            }
        }

        // ---- write partial sums ----
        {
            float2 v;
            int pb = g * 64 + bbase;
            v = unpk(a00); psm[(pb + 0)  * PST + rg]     = v.x + v.y;
            v = unpk(a01); psm[(pb + 4)  * PST + rg]     = v.x + v.y;
            v = unpk(a02); psm[(pb + 8)  * PST + rg]     = v.x + v.y;
            v = unpk(a03); psm[(pb + 12) * PST + rg]     = v.x + v.y;
            v = unpk(a10); psm[(pb + 0)  * PST + rg + 8] = v.x + v.y;
            v = unpk(a11); psm[(pb + 4)  * PST + rg + 8] = v.x + v.y;
            v = unpk(a12); psm[(pb + 8)  * PST + rg + 8] = v.x + v.y;
            v = unpk(a13); psm[(pb + 12) * PST + rg + 8] = v.x + v.y;
        }
        __syncthreads();

        // ---- epilogue: gates -> (h, c); publish h ----
        if (tid < 256) {
            int b = tid & 63, u = tid >> 6;
            float pre[4];
            #pragma unroll
            for (int gg = 0; gg < 4; ++gg) {
                int r = u * 4 + gg;
                pre[gg] = bsm[r]
                        + psm[(0 * 64 + b) * PST + r]
                        + psm[(1 * 64 + b) * PST + r]
                        + psm[(2 * 64 + b) * PST + r]
                        + psm[(3 * 64 + b) * PST + r];
            }
            float fg  = sigmoidf_(pre[0]);
            float ig  = sigmoidf_(pre[1]);
            float gg2 = tanhf(pre[2]);
            float og  = sigmoidf_(pre[3]);
            float c   = fg * csm[tid] + ig * gg2;
            csm[tid]  = c;
            float h   = og * tanhf(c);
            g_h[p ^ 1][b * HID + j0 + u] = h;      // plain store (R3-proven)
            out[((size_t)t * BATCH + b) * HID + j0 + u] = h;
            if (t == SEQ - 1) {
                size_t base = (size_t)SEQ * BATCH * HID;
                out[base + (size_t)b * HID + j0 + u] = h;
                out[base + (size_t)BATCH * HID + (size_t)b * HID + j0 + u] = c;
            }
            __threadfence();                       // writer-side release
        }
        __syncthreads();
        if (tid == 0) {
            __threadfence();                       // signaler-side release
            g_flags[bid * 64] = (unsigned)(t + 2); // volatile store
        }
    }

    // ---- reset persistent state for the next graph replay ----
    __syncthreads();
    if (tid == 0) {
        __threadfence();
        if (atomicAdd(&g_done, 1u) == NBLK - 1) {
            g_done = 0u;
            for (int i = 0; i < NBLK; ++i) g_flags[i * 64] = 0u;
            __threadfence();
        }
    }
}

extern "C" void kernel_launch(void* const* d_in, const int* in_sizes, int n_in,
                              void* d_out, int out_size)
{
    const float* x  = (const float*)d_in[0];
    const float* Wf = (const float*)d_in[1];
    const float* bf = (const float*)d_in[2];
    const float* Wi = (const float*)d_in[3];
    const float* bi = (const float*)d_in[4];
    const float* Wg = (const float*)d_in[5];
    const float* bg = (const float*)d_in[6];
    const float* Wo = (const float*)d_in[7];
    const float* bo = (const float*)d_in[8];
    float* out = (float*)d_out;

    cudaFuncSetAttribute(lstm_kernel,
                         cudaFuncAttributeMaxDynamicSharedMemorySize, SMEM_BYTES);
    lstm_kernel<<<NBLK, NTHR, SMEM_BYTES>>>(x, Wf, bf, Wi, bi, Wg, bg, Wo, bo, out);
}